// round 1
// baseline (speedup 1.0000x reference)
#include <cuda_runtime.h>
#include <cuda_bf16.h>

#define NROW 4096
#define DDIM 2048
#define EPSF 1e-5f

#define BM 128
#define BN 128
#define BK 16
#define NTILE (NROW / BM)  // 32

// Scratch (no allocations allowed): normalized x + per-row accumulators.
__device__ float g_xn[NROW * DDIM];   // 32 MB
__device__ float g_acc[NROW * 8];     // 8 accumulators per row:
// [0]=sum pos_intra val [1]=cnt pos_intra
// [2]=sum pos_cross val [3]=cnt pos_cross
// [4]=num neg_intra     [5]=den neg_intra
// [6]=num neg_cross     [7]=den neg_cross

// ---------------------------------------------------------------------------
// Kernel 1: L2-normalize each row of x into g_xn; zero g_acc.
// One block per row, 256 threads, 2048 floats = 2 float4 per thread.
// ---------------------------------------------------------------------------
__global__ __launch_bounds__(256) void normalize_kernel(const float* __restrict__ x) {
    int row = blockIdx.x;
    int t = threadIdx.x;
    const float4* xr = (const float4*)(x + (size_t)row * DDIM);
    float4* xo = (float4*)(g_xn + (size_t)row * DDIM);

    float4 v0 = xr[t];
    float4 v1 = xr[t + 256];
    float ss = v0.x * v0.x + v0.y * v0.y + v0.z * v0.z + v0.w * v0.w
             + v1.x * v1.x + v1.y * v1.y + v1.z * v1.z + v1.w * v1.w;
#pragma unroll
    for (int o = 16; o > 0; o >>= 1) ss += __shfl_xor_sync(0xffffffffu, ss, o);

    __shared__ float warpSum[8];
    __shared__ float totS;
    if ((t & 31) == 0) warpSum[t >> 5] = ss;
    __syncthreads();
    if (t == 0) {
        float tot = 0.f;
#pragma unroll
        for (int i = 0; i < 8; i++) tot += warpSum[i];
        totS = tot;
    }
    __syncthreads();

    float rinv = 1.0f / fmaxf(sqrtf(totS), 1e-12f);
    v0.x *= rinv; v0.y *= rinv; v0.z *= rinv; v0.w *= rinv;
    v1.x *= rinv; v1.y *= rinv; v1.z *= rinv; v1.w *= rinv;
    xo[t] = v0;
    xo[t + 256] = v1;

    if (t < 8) g_acc[row * 8 + t] = 0.f;
}

// ---------------------------------------------------------------------------
// Kernel 2: fused triangular Gram + loss epilogue.
// Grid = NTILE*(NTILE+1)/2 blocks; block (bi,bj) with bi<=bj computes the
// 128x128 dot-product tile, converts to distances, classifies with
// (targets, sub) masks, and accumulates per-row partial sums. Off-diagonal
// tiles also credit the symmetric (column) rows.
// ---------------------------------------------------------------------------
__global__ __launch_bounds__(256) void fused_kernel(const int* __restrict__ targets,
                                                    const int* __restrict__ sub) {
    __shared__ float As[BK][BM];
    __shared__ float Bs[BK][BN];
    __shared__ float rowAcc[BM][8];
    __shared__ float colAcc[BN][8];
    __shared__ int tI[BM], sI[BM], tJ[BN], sJ[BN];

    // Triangular block decode: blockIdx.x -> (bi, bj), bi <= bj
    int bi = 0, rem = blockIdx.x;
    while (rem >= NTILE - bi) { rem -= NTILE - bi; bi++; }
    int bj = bi + rem;
    bool diag = (bi == bj);

    int tid = threadIdx.x;
    int tx = tid & 15;       // 16 column groups of 8
    int ty = tid >> 4;       // 16 row groups of 8

    for (int i = tid; i < BM * 8; i += 256) {
        ((float*)rowAcc)[i] = 0.f;
        ((float*)colAcc)[i] = 0.f;
    }
    if (tid < BM) {
        tI[tid] = targets[bi * BM + tid];
        sI[tid] = sub[bi * BM + tid];
        tJ[tid] = targets[bj * BN + tid];
        sJ[tid] = sub[bj * BN + tid];
    }

    const float* A  = g_xn + (size_t)bi * BM * DDIM;
    const float* Bp = g_xn + (size_t)bj * BN * DDIM;

    float acc[8][8];
#pragma unroll
    for (int m = 0; m < 8; m++)
#pragma unroll
        for (int n = 0; n < 8; n++) acc[m][n] = 0.f;

    for (int k0 = 0; k0 < DDIM; k0 += BK) {
        // Load 128x16 tiles of A and B (512 float4 each; 2 per thread),
        // storing k-major (transposed) into shared.
#pragma unroll
        for (int l = 0; l < 2; l++) {
            int f  = tid + l * 256;
            int r  = f >> 2;          // row 0..127
            int kq = (f & 3) << 2;    // k offset 0,4,8,12
            float4 va = *(const float4*)(A + (size_t)r * DDIM + k0 + kq);
            As[kq + 0][r] = va.x; As[kq + 1][r] = va.y;
            As[kq + 2][r] = va.z; As[kq + 3][r] = va.w;
            float4 vb = *(const float4*)(Bp + (size_t)r * DDIM + k0 + kq);
            Bs[kq + 0][r] = vb.x; Bs[kq + 1][r] = vb.y;
            Bs[kq + 2][r] = vb.z; Bs[kq + 3][r] = vb.w;
        }
        __syncthreads();
#pragma unroll
        for (int kk = 0; kk < BK; kk++) {
            float am[8], bn[8];
#pragma unroll
            for (int m = 0; m < 8; m++) am[m] = As[kk][ty * 8 + m];
#pragma unroll
            for (int n = 0; n < 8; n++) bn[n] = Bs[kk][tx * 8 + n];
#pragma unroll
            for (int m = 0; m < 8; m++)
#pragma unroll
                for (int n = 0; n < 8; n++)
                    acc[m][n] = fmaf(am[m], bn[n], acc[m][n]);
        }
        __syncthreads();
    }

    // ---- Epilogue: row-direction pass ----
    int i0 = bi * BM + ty * 8;
    int j0 = bj * BN + tx * 8;
#pragma unroll
    for (int m = 0; m < 8; m++) {
        int li = ty * 8 + m;
        int gi = i0 + m;
        int ti = tI[li], si = sI[li];
        float p0 = 0.f, p1 = 0.f, p2 = 0.f, p3 = 0.f;
        float p4 = 0.f, p5 = 0.f, p6 = 0.f, p7 = 0.f;
#pragma unroll
        for (int n = 0; n < 8; n++) {
            int lj = tx * 8 + n;
            int gj = j0 + n;
            float d = sqrtf(fmaxf(2.f - 2.f * acc[m][n], 1e-12f));
            bool same  = (ti == tJ[lj]);
            bool intra = (si == sJ[lj]);
            if (same) {
                if (gi != gj) {
                    if (intra) { p0 += fmaxf(d - 1.4f, 0.f); p1 += 1.f; }
                    else       { p2 += fmaxf(d - 0.7f, 0.f); p3 += 1.f; }
                }
            } else {
                float alpha = intra ? 2.4f : 2.2f;
                if (d < alpha) {
                    float diff = alpha - d;
                    float w = __expf(diff);
                    if (intra) { p4 += diff * w; p5 += w; }
                    else       { p6 += diff * w; p7 += w; }
                }
            }
        }
        if (p1 != 0.f) { atomicAdd(&rowAcc[li][0], p0); atomicAdd(&rowAcc[li][1], p1); }
        if (p3 != 0.f) { atomicAdd(&rowAcc[li][2], p2); atomicAdd(&rowAcc[li][3], p3); }
        if (p5 != 0.f) { atomicAdd(&rowAcc[li][4], p4); atomicAdd(&rowAcc[li][5], p5); }
        if (p7 != 0.f) { atomicAdd(&rowAcc[li][6], p6); atomicAdd(&rowAcc[li][7], p7); }
    }

    // ---- Epilogue: column-direction pass (symmetry credit), off-diag only ----
    if (!diag) {
#pragma unroll
        for (int n = 0; n < 8; n++) {
            int lj = tx * 8 + n;
            int tj = tJ[lj], sj = sJ[lj];
            float p0 = 0.f, p1 = 0.f, p2 = 0.f, p3 = 0.f;
            float p4 = 0.f, p5 = 0.f, p6 = 0.f, p7 = 0.f;
#pragma unroll
            for (int m = 0; m < 8; m++) {
                int li = ty * 8 + m;
                float d = sqrtf(fmaxf(2.f - 2.f * acc[m][n], 1e-12f));
                bool same  = (tI[li] == tj);
                bool intra = (sI[li] == sj);
                if (same) {
                    // bi < bj here, so global i != global j always
                    if (intra) { p0 += fmaxf(d - 1.4f, 0.f); p1 += 1.f; }
                    else       { p2 += fmaxf(d - 0.7f, 0.f); p3 += 1.f; }
                } else {
                    float alpha = intra ? 2.4f : 2.2f;
                    if (d < alpha) {
                        float diff = alpha - d;
                        float w = __expf(diff);
                        if (intra) { p4 += diff * w; p5 += w; }
                        else       { p6 += diff * w; p7 += w; }
                    }
                }
            }
            if (p1 != 0.f) { atomicAdd(&colAcc[lj][0], p0); atomicAdd(&colAcc[lj][1], p1); }
            if (p3 != 0.f) { atomicAdd(&colAcc[lj][2], p2); atomicAdd(&colAcc[lj][3], p3); }
            if (p5 != 0.f) { atomicAdd(&colAcc[lj][4], p4); atomicAdd(&colAcc[lj][5], p5); }
            if (p7 != 0.f) { atomicAdd(&colAcc[lj][6], p6); atomicAdd(&colAcc[lj][7], p7); }
        }
    }

    __syncthreads();

    // ---- Flush block partials to global accumulators ----
    for (int i = tid; i < BM * 8; i += 256) {
        int r = i >> 3, s = i & 7;
        float v = ((float*)rowAcc)[i];
        if (v != 0.f) atomicAdd(&g_acc[(bi * BM + r) * 8 + s], v);
        if (!diag) {
            float vc = ((float*)colAcc)[i];
            if (vc != 0.f) atomicAdd(&g_acc[(bj * BN + r) * 8 + s], vc);
        }
    }
}

// ---------------------------------------------------------------------------
// Kernel 3: finalize — per-row loss, then mean over rows.
// ---------------------------------------------------------------------------
__global__ __launch_bounds__(256) void finalize_kernel(float* __restrict__ out) {
    int t = threadIdx.x;
    float s = 0.f;
    for (int r = t; r < NROW; r += 256) {
        const float* a = g_acc + r * 8;
        s += a[0] / (a[1] + EPSF) + a[2] / (a[3] + EPSF)
           + a[4] / (a[5] + EPSF) + a[6] / (a[7] + EPSF);
    }
#pragma unroll
    for (int o = 16; o > 0; o >>= 1) s += __shfl_xor_sync(0xffffffffu, s, o);
    __shared__ float ws[8];
    if ((t & 31) == 0) ws[t >> 5] = s;
    __syncthreads();
    if (t == 0) {
        float tot = 0.f;
#pragma unroll
        for (int i = 0; i < 8; i++) tot += ws[i];
        out[0] = tot / (float)NROW;
    }
}

extern "C" void kernel_launch(void* const* d_in, const int* in_sizes, int n_in,
                              void* d_out, int out_size) {
    const float* x       = (const float*)d_in[0];
    const int*   targets = (const int*)d_in[1];
    const int*   sub     = (const int*)d_in[2];

    normalize_kernel<<<NROW, 256>>>(x);
    fused_kernel<<<(NTILE * (NTILE + 1)) / 2, 256>>>(targets, sub);
    finalize_kernel<<<1, 256>>>((float*)d_out);
}

// round 2
// speedup vs baseline: 3.8420x; 3.8420x over previous
#include <cuda_runtime.h>
#include <cuda_bf16.h>
#include <cstdint>

#define NROW 4096
#define DDIM 2048
#define EPSF 1e-5f

#define BM 128
#define BN 128
#define BKH 32                 // k-chunk in halves
#define NTILE (NROW / BM)      // 32

// Scratch: normalized x in bf16 + per-row accumulators.
__device__ __nv_bfloat16 g_xb[NROW * DDIM];   // 16 MB
__device__ float g_acc[NROW * 8];
// [0]=sum pos_intra [1]=cnt pos_intra [2]=sum pos_cross [3]=cnt pos_cross
// [4]=num neg_intra [5]=den neg_intra [6]=num neg_cross [7]=den neg_cross

#define LDSM_X4(R0, R1, R2, R3, addr)                                          \
    asm volatile("ldmatrix.sync.aligned.m8n8.x4.shared.b16 {%0,%1,%2,%3}, [%4];" \
                 : "=r"(R0), "=r"(R1), "=r"(R2), "=r"(R3) : "r"(addr))

#define MMA16816(D, A, B)                                                      \
    asm volatile("mma.sync.aligned.m16n8k16.row.col.f32.bf16.bf16.f32 "        \
                 "{%0,%1,%2,%3},{%4,%5,%6,%7},{%8,%9},{%0,%1,%2,%3};"          \
                 : "+f"((D)[0]), "+f"((D)[1]), "+f"((D)[2]), "+f"((D)[3])      \
                 : "r"((A)[0]), "r"((A)[1]), "r"((A)[2]), "r"((A)[3]),         \
                   "r"((B)[0]), "r"((B)[1]))

// ---------------------------------------------------------------------------
// Kernel 1: L2-normalize rows (fp32 math) -> bf16 g_xb; zero g_acc.
// ---------------------------------------------------------------------------
__global__ __launch_bounds__(256) void normalize_kernel(const float* __restrict__ x) {
    int row = blockIdx.x;
    int t = threadIdx.x;
    const float4* xr = (const float4*)(x + (size_t)row * DDIM);

    float4 v0 = xr[2 * t];
    float4 v1 = xr[2 * t + 1];
    float ss = v0.x * v0.x + v0.y * v0.y + v0.z * v0.z + v0.w * v0.w
             + v1.x * v1.x + v1.y * v1.y + v1.z * v1.z + v1.w * v1.w;
#pragma unroll
    for (int o = 16; o > 0; o >>= 1) ss += __shfl_xor_sync(0xffffffffu, ss, o);

    __shared__ float warpSum[8];
    __shared__ float totS;
    if ((t & 31) == 0) warpSum[t >> 5] = ss;
    __syncthreads();
    if (t == 0) {
        float tot = 0.f;
#pragma unroll
        for (int i = 0; i < 8; i++) tot += warpSum[i];
        totS = tot;
    }
    __syncthreads();

    float rinv = 1.0f / fmaxf(sqrtf(totS), 1e-12f);
    union { uint4 u; __nv_bfloat162 h[4]; } pk;
    pk.h[0] = __floats2bfloat162_rn(v0.x * rinv, v0.y * rinv);
    pk.h[1] = __floats2bfloat162_rn(v0.z * rinv, v0.w * rinv);
    pk.h[2] = __floats2bfloat162_rn(v1.x * rinv, v1.y * rinv);
    pk.h[3] = __floats2bfloat162_rn(v1.z * rinv, v1.w * rinv);
    *(uint4*)(g_xb + (size_t)row * DDIM + 8 * t) = pk.u;

    if (t < 8) g_acc[row * 8 + t] = 0.f;
}

// ---------------------------------------------------------------------------
// Kernel 2: triangular Gram via bf16 tensor cores + fused loss epilogue.
// 256 threads = 8 warps (4 m x 2 n); warp tile 32x64; BK=32.
// ---------------------------------------------------------------------------
__global__ __launch_bounds__(256) void fused_kernel(const int* __restrict__ targets,
                                                    const int* __restrict__ sub) {
    __shared__ __align__(16) __nv_bfloat16 As[BM * BKH];  // [m][k], chunk-swizzled
    __shared__ __align__(16) __nv_bfloat16 Bs[BN * BKH];  // [n][k], chunk-swizzled
    __shared__ float rowAcc[BM][8];
    __shared__ float colAcc[BN][8];
    __shared__ int tI[BM], sI[BM], tJ[BN], sJ[BN];

    // Triangular decode: blockIdx.x -> (bi, bj), bi <= bj
    int bi = 0, rem = blockIdx.x;
    while (rem >= NTILE - bi) { rem -= NTILE - bi; bi++; }
    int bj = bi + rem;
    bool diag = (bi == bj);

    int tid = threadIdx.x;
    int lane = tid & 31;
    int wid = tid >> 5;
    int warp_m = wid & 3;   // m offset 32*warp_m
    int warp_n = wid >> 2;  // n offset 64*warp_n

    for (int i = tid; i < BM * 8; i += 256) {
        ((float*)rowAcc)[i] = 0.f;
        ((float*)colAcc)[i] = 0.f;
    }
    if (tid < BM) {
        tI[tid] = targets[bi * BM + tid];
        sI[tid] = sub[bi * BM + tid];
        tJ[tid] = targets[bj * BN + tid];
        sJ[tid] = sub[bj * BN + tid];
    }

    const __nv_bfloat16* Ag = g_xb + (size_t)(bi * BM) * DDIM;
    const __nv_bfloat16* Bg = g_xb + (size_t)(bj * BN) * DDIM;

    uint32_t asA = (uint32_t)__cvta_generic_to_shared(As);
    uint32_t asB = (uint32_t)__cvta_generic_to_shared(Bs);

    float acc[2][8][4];
#pragma unroll
    for (int mt = 0; mt < 2; mt++)
#pragma unroll
        for (int nt = 0; nt < 8; nt++)
#pragma unroll
            for (int e = 0; e < 4; e++) acc[mt][nt][e] = 0.f;

    for (int k0 = 0; k0 < DDIM; k0 += BKH) {
        // Load 128x32 bf16 tiles: 512 x 16B; 2 per thread per tile.
        // Swizzle: physical chunk = c ^ ((r>>1)&3) -> conflict-free stores + ldmatrix.
#pragma unroll
        for (int l = 0; l < 2; l++) {
            int idx = l * 256 + tid;
            int r = idx >> 2;
            int c = idx & 3;
            int cp = c ^ ((r >> 1) & 3);
            uint4 va = *(const uint4*)(Ag + (size_t)r * DDIM + k0 + c * 8);
            *(uint4*)(As + r * BKH + cp * 8) = va;
            uint4 vb = *(const uint4*)(Bg + (size_t)r * DDIM + k0 + c * 8);
            *(uint4*)(Bs + r * BKH + cp * 8) = vb;
        }
        __syncthreads();

#pragma unroll
        for (int ks = 0; ks < 2; ks++) {
            int kk = ks * 16;
            uint32_t a[2][4];
#pragma unroll
            for (int mt = 0; mt < 2; mt++) {
                int r = warp_m * 32 + mt * 16 + (lane & 15);
                int ce = (kk >> 3) + (lane >> 4);
                int cp = ce ^ ((r >> 1) & 3);
                uint32_t addr = asA + (uint32_t)(r * BKH + cp * 8) * 2;
                LDSM_X4(a[mt][0], a[mt][1], a[mt][2], a[mt][3], addr);
            }
            uint32_t b[8][2];
#pragma unroll
            for (int np = 0; np < 4; np++) {
                int r = warp_n * 64 + np * 16 + ((lane & 7) | ((lane >> 4) << 3));
                int ce = (kk >> 3) + ((lane >> 3) & 1);
                int cp = ce ^ ((r >> 1) & 3);
                uint32_t addr = asB + (uint32_t)(r * BKH + cp * 8) * 2;
                LDSM_X4(b[np * 2][0], b[np * 2][1], b[np * 2 + 1][0], b[np * 2 + 1][1], addr);
            }
#pragma unroll
            for (int mt = 0; mt < 2; mt++)
#pragma unroll
                for (int nt = 0; nt < 8; nt++)
                    MMA16816(acc[mt][nt], a[mt], b[nt]);
        }
        __syncthreads();
    }

    // Convert dots -> distances in place.
#pragma unroll
    for (int mt = 0; mt < 2; mt++)
#pragma unroll
        for (int nt = 0; nt < 8; nt++)
#pragma unroll
            for (int e = 0; e < 4; e++)
                acc[mt][nt][e] = sqrtf(fmaxf(2.f - 2.f * acc[mt][nt][e], 1e-12f));

    // Fragment layout: element (mt,nt,e): row = warp_m*32 + mt*16 + (e>>1)*8 + lane/4
    //                                     col = warp_n*64 + nt*8 + (lane&3)*2 + (e&1)

    // ---- Row pass ----
#pragma unroll
    for (int mt = 0; mt < 2; mt++) {
#pragma unroll
        for (int h = 0; h < 2; h++) {
            int li = warp_m * 32 + mt * 16 + h * 8 + (lane >> 2);
            int gi = bi * BM + li;
            int ti = tI[li], si = sI[li];
            float p0 = 0.f, p1 = 0.f, p2 = 0.f, p3 = 0.f;
            float p4 = 0.f, p5 = 0.f, p6 = 0.f, p7 = 0.f;
#pragma unroll
            for (int nt = 0; nt < 8; nt++) {
#pragma unroll
                for (int cc = 0; cc < 2; cc++) {
                    int lj = warp_n * 64 + nt * 8 + (lane & 3) * 2 + cc;
                    int gj = bj * BN + lj;
                    float d = acc[mt][nt][h * 2 + cc];
                    bool same = (ti == tJ[lj]);
                    bool intra = (si == sJ[lj]);
                    if (same) {
                        if (gi != gj) {
                            if (intra) { p0 += fmaxf(d - 1.4f, 0.f); p1 += 1.f; }
                            else       { p2 += fmaxf(d - 0.7f, 0.f); p3 += 1.f; }
                        }
                    } else {
                        float alpha = intra ? 2.4f : 2.2f;
                        if (d < alpha) {
                            float diff = alpha - d;
                            float w = __expf(diff);
                            if (intra) { p4 += diff * w; p5 += w; }
                            else       { p6 += diff * w; p7 += w; }
                        }
                    }
                }
            }
            // Quad reduce (lanes sharing a row).
#pragma unroll
            for (int o = 1; o <= 2; o <<= 1) {
                p0 += __shfl_xor_sync(0xffffffffu, p0, o);
                p1 += __shfl_xor_sync(0xffffffffu, p1, o);
                p2 += __shfl_xor_sync(0xffffffffu, p2, o);
                p3 += __shfl_xor_sync(0xffffffffu, p3, o);
                p4 += __shfl_xor_sync(0xffffffffu, p4, o);
                p5 += __shfl_xor_sync(0xffffffffu, p5, o);
                p6 += __shfl_xor_sync(0xffffffffu, p6, o);
                p7 += __shfl_xor_sync(0xffffffffu, p7, o);
            }
            if ((lane & 3) == 0) {
                if (p1 != 0.f) { atomicAdd(&rowAcc[li][0], p0); atomicAdd(&rowAcc[li][1], p1); }
                if (p3 != 0.f) { atomicAdd(&rowAcc[li][2], p2); atomicAdd(&rowAcc[li][3], p3); }
                if (p5 != 0.f) { atomicAdd(&rowAcc[li][4], p4); atomicAdd(&rowAcc[li][5], p5); }
                if (p7 != 0.f) { atomicAdd(&rowAcc[li][6], p6); atomicAdd(&rowAcc[li][7], p7); }
            }
        }
    }

    // ---- Column pass (symmetry credit), off-diagonal only ----
    if (!diag) {
#pragma unroll
        for (int nt = 0; nt < 8; nt++) {
#pragma unroll
            for (int cc = 0; cc < 2; cc++) {
                int lj = warp_n * 64 + nt * 8 + (lane & 3) * 2 + cc;
                int tj = tJ[lj], sj = sJ[lj];
                float p0 = 0.f, p1 = 0.f, p2 = 0.f, p3 = 0.f;
                float p4 = 0.f, p5 = 0.f, p6 = 0.f, p7 = 0.f;
#pragma unroll
                for (int mt = 0; mt < 2; mt++) {
#pragma unroll
                    for (int h = 0; h < 2; h++) {
                        int li = warp_m * 32 + mt * 16 + h * 8 + (lane >> 2);
                        float d = acc[mt][nt][h * 2 + cc];
                        bool same = (tI[li] == tj);
                        bool intra = (sI[li] == sj);
                        if (same) {
                            // bi < bj => global i != global j
                            if (intra) { p0 += fmaxf(d - 1.4f, 0.f); p1 += 1.f; }
                            else       { p2 += fmaxf(d - 0.7f, 0.f); p3 += 1.f; }
                        } else {
                            float alpha = intra ? 2.4f : 2.2f;
                            if (d < alpha) {
                                float diff = alpha - d;
                                float w = __expf(diff);
                                if (intra) { p4 += diff * w; p5 += w; }
                                else       { p6 += diff * w; p7 += w; }
                            }
                        }
                    }
                }
                // Reduce over lanes sharing a column (xor 4,8,16).
#pragma unroll
                for (int o = 4; o <= 16; o <<= 1) {
                    p0 += __shfl_xor_sync(0xffffffffu, p0, o);
                    p1 += __shfl_xor_sync(0xffffffffu, p1, o);
                    p2 += __shfl_xor_sync(0xffffffffu, p2, o);
                    p3 += __shfl_xor_sync(0xffffffffu, p3, o);
                    p4 += __shfl_xor_sync(0xffffffffu, p4, o);
                    p5 += __shfl_xor_sync(0xffffffffu, p5, o);
                    p6 += __shfl_xor_sync(0xffffffffu, p6, o);
                    p7 += __shfl_xor_sync(0xffffffffu, p7, o);
                }
                if (lane < 4) {
                    if (p1 != 0.f) { atomicAdd(&colAcc[lj][0], p0); atomicAdd(&colAcc[lj][1], p1); }
                    if (p3 != 0.f) { atomicAdd(&colAcc[lj][2], p2); atomicAdd(&colAcc[lj][3], p3); }
                    if (p5 != 0.f) { atomicAdd(&colAcc[lj][4], p4); atomicAdd(&colAcc[lj][5], p5); }
                    if (p7 != 0.f) { atomicAdd(&colAcc[lj][6], p6); atomicAdd(&colAcc[lj][7], p7); }
                }
            }
        }
    }

    __syncthreads();

    // Flush block partials to global accumulators.
    for (int i = tid; i < BM * 8; i += 256) {
        int r = i >> 3, s = i & 7;
        float v = ((float*)rowAcc)[i];
        if (v != 0.f) atomicAdd(&g_acc[(bi * BM + r) * 8 + s], v);
        if (!diag) {
            float vc = ((float*)colAcc)[i];
            if (vc != 0.f) atomicAdd(&g_acc[(bj * BN + r) * 8 + s], vc);
        }
    }
}

// ---------------------------------------------------------------------------
// Kernel 3: finalize — per-row loss, mean over rows.
// ---------------------------------------------------------------------------
__global__ __launch_bounds__(256) void finalize_kernel(float* __restrict__ out) {
    int t = threadIdx.x;
    float s = 0.f;
    for (int r = t; r < NROW; r += 256) {
        const float* a = g_acc + r * 8;
        s += a[0] / (a[1] + EPSF) + a[2] / (a[3] + EPSF)
           + a[4] / (a[5] + EPSF) + a[6] / (a[7] + EPSF);
    }
#pragma unroll
    for (int o = 16; o > 0; o >>= 1) s += __shfl_xor_sync(0xffffffffu, s, o);
    __shared__ float ws[8];
    if ((t & 31) == 0) ws[t >> 5] = s;
    __syncthreads();
    if (t == 0) {
        float tot = 0.f;
#pragma unroll
        for (int i = 0; i < 8; i++) tot += ws[i];
        out[0] = tot / (float)NROW;
    }
}

extern "C" void kernel_launch(void* const* d_in, const int* in_sizes, int n_in,
                              void* d_out, int out_size) {
    const float* x       = (const float*)d_in[0];
    const int*   targets = (const int*)d_in[1];
    const int*   sub     = (const int*)d_in[2];

    normalize_kernel<<<NROW, 256>>>(x);
    fused_kernel<<<(NTILE * (NTILE + 1)) / 2, 256>>>(targets, sub);
    finalize_kernel<<<1, 256>>>((float*)d_out);
}

// round 5
// speedup vs baseline: 6.8885x; 1.7929x over previous
#include <cuda_runtime.h>
#include <cuda_bf16.h>
#include <cstdint>

#define NROW 4096
#define DDIM 2048
#define EPSF 1e-5f

#define BM 128
#define BN 128
#define BKH 64                  // halves per k-chunk (128 bytes/row)
#define NCHUNK (DDIM / BKH)     // 32
#define NSTAGE 3
#define TILEB (BM * 128)        // 16 KB per operand tile
#define STAGEB (2 * TILEB)      // 32 KB per stage
#define NTILE (NROW / BM)       // 32

__device__ __nv_bfloat16 g_xb[NROW * DDIM];   // 16 MB normalized bf16
__device__ float g_acc[NROW * 8];
// [0]=sum pos_intra [1]=cnt pos_intra [2]=sum pos_cross [3]=cnt pos_cross
// [4]=num neg_intra [5]=den neg_intra [6]=num neg_cross [7]=den neg_cross

#define LDSM_X4(R0, R1, R2, R3, addr)                                          \
    asm volatile("ldmatrix.sync.aligned.m8n8.x4.shared.b16 {%0,%1,%2,%3}, [%4];" \
                 : "=r"(R0), "=r"(R1), "=r"(R2), "=r"(R3) : "r"(addr))

#define MMA16816(D, A, B)                                                      \
    asm volatile("mma.sync.aligned.m16n8k16.row.col.f32.bf16.bf16.f32 "        \
                 "{%0,%1,%2,%3},{%4,%5,%6,%7},{%8,%9},{%0,%1,%2,%3};"          \
                 : "+f"((D)[0]), "+f"((D)[1]), "+f"((D)[2]), "+f"((D)[3])      \
                 : "r"((A)[0]), "r"((A)[1]), "r"((A)[2]), "r"((A)[3]),         \
                   "r"((B)[0]), "r"((B)[1]))

__device__ __forceinline__ void cp_async16(uint32_t dst, const void* src) {
    asm volatile("cp.async.cg.shared.global [%0], [%1], 16;"
                 :: "r"(dst), "l"(src) : "memory");
}

// ---------------------------------------------------------------------------
// Kernel 1: L2-normalize rows -> bf16 g_xb; zero g_acc.
// ---------------------------------------------------------------------------
__global__ __launch_bounds__(256) void normalize_kernel(const float* __restrict__ x) {
    int row = blockIdx.x;
    int t = threadIdx.x;
    const float4* xr = (const float4*)(x + (size_t)row * DDIM);

    float4 v0 = xr[2 * t];
    float4 v1 = xr[2 * t + 1];
    float ss = v0.x * v0.x + v0.y * v0.y + v0.z * v0.z + v0.w * v0.w
             + v1.x * v1.x + v1.y * v1.y + v1.z * v1.z + v1.w * v1.w;
#pragma unroll
    for (int o = 16; o > 0; o >>= 1) ss += __shfl_xor_sync(0xffffffffu, ss, o);

    __shared__ float warpSum[8];
    __shared__ float totS;
    if ((t & 31) == 0) warpSum[t >> 5] = ss;
    __syncthreads();
    if (t == 0) {
        float tot = 0.f;
#pragma unroll
        for (int i = 0; i < 8; i++) tot += warpSum[i];
        totS = tot;
    }
    __syncthreads();

    float rinv = 1.0f / fmaxf(sqrtf(totS), 1e-12f);
    union { uint4 u; __nv_bfloat162 h[4]; } pk;
    pk.h[0] = __floats2bfloat162_rn(v0.x * rinv, v0.y * rinv);
    pk.h[1] = __floats2bfloat162_rn(v0.z * rinv, v0.w * rinv);
    pk.h[2] = __floats2bfloat162_rn(v1.x * rinv, v1.y * rinv);
    pk.h[3] = __floats2bfloat162_rn(v1.z * rinv, v1.w * rinv);
    *(uint4*)(g_xb + (size_t)row * DDIM + 8 * t) = pk.u;

    if (t < 8) g_acc[row * 8 + t] = 0.f;
}

// ---------------------------------------------------------------------------
// Kernel 2: triangular Gram (mma.sync bf16, 3-stage cp.async) + loss epilogue.
// 256 threads = 8 warps (4 m x 2 n); warp tile 32x64.
// ---------------------------------------------------------------------------
extern __shared__ char dynsmem[];

__global__ __launch_bounds__(256) void fused_kernel(const int* __restrict__ targets,
                                                    const int* __restrict__ sub) {
    __shared__ float rowAcc[BM][8];
    __shared__ float colAcc[BN][8];
    __shared__ int tI[BM], sI[BM], tJ[BN], sJ[BN];

    // Triangular decode: blockIdx.x -> (bi, bj), bi <= bj
    int bi = 0, rem = blockIdx.x;
    while (rem >= NTILE - bi) { rem -= NTILE - bi; bi++; }
    int bj = bi + rem;
    bool diag = (bi == bj);

    int tid = threadIdx.x;
    int lane = tid & 31;
    int wid = tid >> 5;
    int warp_m = wid & 3;   // m offset 32*warp_m
    int warp_n = wid >> 2;  // n offset 64*warp_n

    uint32_t dynb = (uint32_t)__cvta_generic_to_shared(dynsmem);
    uint32_t base = (dynb + 1023u) & ~1023u;

    for (int i = tid; i < BM * 8; i += 256) {
        ((float*)rowAcc)[i] = 0.f;
        ((float*)colAcc)[i] = 0.f;
    }
    if (tid < BM) {
        tI[tid] = targets[bi * BM + tid];
        sI[tid] = sub[bi * BM + tid];
        tJ[tid] = targets[bj * BN + tid];
        sJ[tid] = sub[bj * BN + tid];
    }

    const __nv_bfloat16* Ag = g_xb + (size_t)(bi * BM) * DDIM;
    const __nv_bfloat16* Bg = g_xb + (size_t)(bj * BN) * DDIM;

    // Per-thread load slots: 4 x 16B per operand per stage.
    // idx = i*256 + tid -> row = idx>>3, chunk c = idx&7, phys chunk = c^(r&7).
    int lrow[4], lcoff[4], lcsw[4];
#pragma unroll
    for (int i = 0; i < 4; i++) {
        int idx = i * 256 + tid;
        lrow[i] = idx >> 3;
        int c = idx & 7;
        lcoff[i] = c * 8;                    // halves offset in gmem row
        lcsw[i] = (c ^ (lrow[i] & 7)) * 16;  // swizzled byte offset in smem row
    }

#define LOAD_STAGE(S, F)                                                           \
    do {                                                                           \
        uint32_t aB = base + (S) * STAGEB;                                         \
        uint32_t bB = aB + TILEB;                                                  \
        int k0 = (F) * BKH;                                                        \
        _Pragma("unroll")                                                          \
        for (int i = 0; i < 4; i++) {                                              \
            int r = lrow[i];                                                       \
            cp_async16(aB + r * 128 + lcsw[i], Ag + (size_t)r * DDIM + k0 + lcoff[i]); \
            cp_async16(bB + r * 128 + lcsw[i], Bg + (size_t)r * DDIM + k0 + lcoff[i]); \
        }                                                                          \
        asm volatile("cp.async.commit_group;" ::: "memory");                       \
    } while (0)

    float acc[2][8][4];
#pragma unroll
    for (int mt = 0; mt < 2; mt++)
#pragma unroll
        for (int nt = 0; nt < 8; nt++)
#pragma unroll
            for (int e = 0; e < 4; e++) acc[mt][nt][e] = 0.f;

    LOAD_STAGE(0, 0);
    LOAD_STAGE(1, 1);

    for (int c = 0; c < NCHUNK; c++) {
        if (c + 2 < NCHUNK) {
            LOAD_STAGE((c + 2) % NSTAGE, c + 2);
            asm volatile("cp.async.wait_group 2;" ::: "memory");
        } else if (c + 1 < NCHUNK) {
            asm volatile("cp.async.wait_group 1;" ::: "memory");
        } else {
            asm volatile("cp.async.wait_group 0;" ::: "memory");
        }
        __syncthreads();

        uint32_t asA = base + (c % NSTAGE) * STAGEB;
        uint32_t asB = asA + TILEB;

#pragma unroll
        for (int ks = 0; ks < 4; ks++) {
            uint32_t a[2][4];
#pragma unroll
            for (int mt = 0; mt < 2; mt++) {
                int r = warp_m * 32 + mt * 16 + (lane & 15);
                int ce = ks * 2 + (lane >> 4);
                int cp = ce ^ (r & 7);
                LDSM_X4(a[mt][0], a[mt][1], a[mt][2], a[mt][3],
                        asA + (uint32_t)(r * 128 + cp * 16));
            }
            uint32_t b[8][2];
#pragma unroll
            for (int np = 0; np < 4; np++) {
                int r = warp_n * 64 + np * 16 + ((lane & 7) | ((lane >> 4) << 3));
                int ce = ks * 2 + ((lane >> 3) & 1);
                int cp = ce ^ (r & 7);
                LDSM_X4(b[np * 2][0], b[np * 2][1], b[np * 2 + 1][0], b[np * 2 + 1][1],
                        asB + (uint32_t)(r * 128 + cp * 16));
            }
#pragma unroll
            for (int mt = 0; mt < 2; mt++)
#pragma unroll
                for (int nt = 0; nt < 8; nt++)
                    MMA16816(acc[mt][nt], a[mt], b[nt]);
        }
        __syncthreads();
    }

    // Convert dots -> distances in place.
#pragma unroll
    for (int mt = 0; mt < 2; mt++)
#pragma unroll
        for (int nt = 0; nt < 8; nt++)
#pragma unroll
            for (int e = 0; e < 4; e++)
                acc[mt][nt][e] = sqrtf(fmaxf(2.f - 2.f * acc[mt][nt][e], 1e-12f));

    // Fragment layout: row = warp_m*32 + mt*16 + (e>>1)*8 + lane/4
    //                  col = warp_n*64 + nt*8 + (lane&3)*2 + (e&1)

    // ---- Row pass ----
#pragma unroll
    for (int mt = 0; mt < 2; mt++) {
#pragma unroll
        for (int h = 0; h < 2; h++) {
            int li = warp_m * 32 + mt * 16 + h * 8 + (lane >> 2);
            int gi = bi * BM + li;
            int ti = tI[li], si = sI[li];
            float p0 = 0.f, p1 = 0.f, p2 = 0.f, p3 = 0.f;
            float p4 = 0.f, p5 = 0.f, p6 = 0.f, p7 = 0.f;
#pragma unroll
            for (int nt = 0; nt < 8; nt++) {
#pragma unroll
                for (int cc = 0; cc < 2; cc++) {
                    int lj = warp_n * 64 + nt * 8 + (lane & 3) * 2 + cc;
                    int gj = bj * BN + lj;
                    float d = acc[mt][nt][h * 2 + cc];
                    bool same = (ti == tJ[lj]);
                    bool intra = (si == sJ[lj]);
                    if (same) {
                        if (gi != gj) {
                            if (intra) { p0 += fmaxf(d - 1.4f, 0.f); p1 += 1.f; }
                            else       { p2 += fmaxf(d - 0.7f, 0.f); p3 += 1.f; }
                        }
                    } else {
                        float alpha = intra ? 2.4f : 2.2f;
                        if (d < alpha) {
                            float diff = alpha - d;
                            float w = __expf(diff);
                            if (intra) { p4 += diff * w; p5 += w; }
                            else       { p6 += diff * w; p7 += w; }
                        }
                    }
                }
            }
#pragma unroll
            for (int o = 1; o <= 2; o <<= 1) {
                p0 += __shfl_xor_sync(0xffffffffu, p0, o);
                p1 += __shfl_xor_sync(0xffffffffu, p1, o);
                p2 += __shfl_xor_sync(0xffffffffu, p2, o);
                p3 += __shfl_xor_sync(0xffffffffu, p3, o);
                p4 += __shfl_xor_sync(0xffffffffu, p4, o);
                p5 += __shfl_xor_sync(0xffffffffu, p5, o);
                p6 += __shfl_xor_sync(0xffffffffu, p6, o);
                p7 += __shfl_xor_sync(0xffffffffu, p7, o);
            }
            if ((lane & 3) == 0) {
                if (p1 != 0.f) { atomicAdd(&rowAcc[li][0], p0); atomicAdd(&rowAcc[li][1], p1); }
                if (p3 != 0.f) { atomicAdd(&rowAcc[li][2], p2); atomicAdd(&rowAcc[li][3], p3); }
                if (p5 != 0.f) { atomicAdd(&rowAcc[li][4], p4); atomicAdd(&rowAcc[li][5], p5); }
                if (p7 != 0.f) { atomicAdd(&rowAcc[li][6], p6); atomicAdd(&rowAcc[li][7], p7); }
            }
        }
    }

    // ---- Column pass (symmetry credit), off-diagonal only ----
    if (!diag) {
#pragma unroll
        for (int nt = 0; nt < 8; nt++) {
#pragma unroll
            for (int cc = 0; cc < 2; cc++) {
                int lj = warp_n * 64 + nt * 8 + (lane & 3) * 2 + cc;
                int tj = tJ[lj], sj = sJ[lj];
                float p0 = 0.f, p1 = 0.f, p2 = 0.f, p3 = 0.f;
                float p4 = 0.f, p5 = 0.f, p6 = 0.f, p7 = 0.f;
#pragma unroll
                for (int mt = 0; mt < 2; mt++) {
#pragma unroll
                    for (int h = 0; h < 2; h++) {
                        int li = warp_m * 32 + mt * 16 + h * 8 + (lane >> 2);
                        float d = acc[mt][nt][h * 2 + cc];
                        bool same = (tI[li] == tj);
                        bool intra = (sI[li] == sj);
                        if (same) {
                            if (intra) { p0 += fmaxf(d - 1.4f, 0.f); p1 += 1.f; }
                            else       { p2 += fmaxf(d - 0.7f, 0.f); p3 += 1.f; }
                        } else {
                            float alpha = intra ? 2.4f : 2.2f;
                            if (d < alpha) {
                                float diff = alpha - d;
                                float w = __expf(diff);
                                if (intra) { p4 += diff * w; p5 += w; }
                                else       { p6 += diff * w; p7 += w; }
                            }
                        }
                    }
                }
#pragma unroll
                for (int o = 4; o <= 16; o <<= 1) {
                    p0 += __shfl_xor_sync(0xffffffffu, p0, o);
                    p1 += __shfl_xor_sync(0xffffffffu, p1, o);
                    p2 += __shfl_xor_sync(0xffffffffu, p2, o);
                    p3 += __shfl_xor_sync(0xffffffffu, p3, o);
                    p4 += __shfl_xor_sync(0xffffffffu, p4, o);
                    p5 += __shfl_xor_sync(0xffffffffu, p5, o);
                    p6 += __shfl_xor_sync(0xffffffffu, p6, o);
                    p7 += __shfl_xor_sync(0xffffffffu, p7, o);
                }
                if (lane < 4) {
                    if (p1 != 0.f) { atomicAdd(&colAcc[lj][0], p0); atomicAdd(&colAcc[lj][1], p1); }
                    if (p3 != 0.f) { atomicAdd(&colAcc[lj][2], p2); atomicAdd(&colAcc[lj][3], p3); }
                    if (p5 != 0.f) { atomicAdd(&colAcc[lj][4], p4); atomicAdd(&colAcc[lj][5], p5); }
                    if (p7 != 0.f) { atomicAdd(&colAcc[lj][6], p6); atomicAdd(&colAcc[lj][7], p7); }
                }
            }
        }
    }

    __syncthreads();

    for (int i = tid; i < BM * 8; i += 256) {
        int r = i >> 3, s = i & 7;
        float v = ((float*)rowAcc)[i];
        if (v != 0.f) atomicAdd(&g_acc[(bi * BM + r) * 8 + s], v);
        if (!diag) {
            float vc = ((float*)colAcc)[i];
            if (vc != 0.f) atomicAdd(&g_acc[(bj * BN + r) * 8 + s], vc);
        }
    }
}

// ---------------------------------------------------------------------------
// Kernel 3: finalize.
// ---------------------------------------------------------------------------
__global__ __launch_bounds__(256) void finalize_kernel(float* __restrict__ out) {
    int t = threadIdx.x;
    float s = 0.f;
    for (int r = t; r < NROW; r += 256) {
        const float* a = g_acc + r * 8;
        s += a[0] / (a[1] + EPSF) + a[2] / (a[3] + EPSF)
           + a[4] / (a[5] + EPSF) + a[6] / (a[7] + EPSF);
    }
#pragma unroll
    for (int o = 16; o > 0; o >>= 1) s += __shfl_xor_sync(0xffffffffu, s, o);
    __shared__ float ws[8];
    if ((t & 31) == 0) ws[t >> 5] = s;
    __syncthreads();
    if (t == 0) {
        float tot = 0.f;
#pragma unroll
        for (int i = 0; i < 8; i++) tot += ws[i];
        out[0] = tot / (float)NROW;
    }
}

extern "C" void kernel_launch(void* const* d_in, const int* in_sizes, int n_in,
                              void* d_out, int out_size) {
    const float* x       = (const float*)d_in[0];
    const int*   targets = (const int*)d_in[1];
    const int*   sub     = (const int*)d_in[2];

    int dyn = 1024 + NSTAGE * STAGEB;  // 97.3 KB
    cudaFuncSetAttribute(fused_kernel, cudaFuncAttributeMaxDynamicSharedMemorySize, dyn);

    normalize_kernel<<<NROW, 256>>>(x);
    fused_kernel<<<(NTILE * (NTILE + 1)) / 2, 256, dyn>>>(targets, sub);
    finalize_kernel<<<1, 256>>>((float*)d_out);
}